// round 15
// baseline (speedup 1.0000x reference)
#include <cuda_runtime.h>
#include <cstdint>

// T = 2000 tags, V = 20000 videos, D = 768, E_POS = E_NEG = 100000
// Output layout: [cls_score (V*T f32), labels (V*T f32)]
//
// R15 = R14 (proven: zero 43us DRAM floor + cp.async edge 52us LTS floor)
// with the 13us scatter_kernel moved onto a FORKED STREAM inside the graph:
//
//      main:   [evA] --- zero_kernel ------------ wait(evB) --- edge_kernel
//      s2  :     \-- wait(evA) -- scatter_kernel -- [evB]
//
// zero writes d_out only; scatter writes g_cursor/g_edges only -> disjoint,
// safe to run concurrently. edge joins both.
// Cursor lifecycle: edge_kernel resets cursor[t] AFTER reading it
// (single-reader broadcast), so replay k's reset precedes replay k+1's
// scatter fill. Module-load zeros cover the very first run.

#define D_DIM    768
#define T_DIM    2000
#define BIN_CAP  192      // edges/tag ~ Poisson(100); P(>192) ~ 1e-12
#define STAGES   2
#define ROW_F4   (D_DIM / 4)     // 192 float4 per row (3072 B)

__device__ int      g_cursor[T_DIM];            // zero at module load
__device__ unsigned g_edges [T_DIM * BIN_CAP];  // bit31 = isPos, low = dst

// ---------------------------------------------------------------------------
__global__ void zero_kernel(float4* __restrict__ out, long long nvec) {
    long long i = (long long)blockIdx.x * blockDim.x + threadIdx.x;
    if (i < nvec)
        __stcs(&out[i], make_float4(0.f, 0.f, 0.f, 0.f));
}

// ---------------------------------------------------------------------------
__global__ void scatter_kernel(const int* __restrict__ pos_src,
                               const int* __restrict__ pos_dst,
                               const int* __restrict__ neg_src,
                               const int* __restrict__ neg_dst,
                               int nPos, int nTot) {
    int i = blockIdx.x * blockDim.x + threadIdx.x;
    if (i < nTot) {
        int t; unsigned enc;
        if (i < nPos) { t = pos_src[i];        enc = (unsigned)pos_dst[i] | 0x80000000u; }
        else          { t = neg_src[i - nPos]; enc = (unsigned)neg_dst[i - nPos]; }
        int slot = atomicAdd(&g_cursor[t], 1);
        if (slot < BIN_CAP)
            g_edges[t * BIN_CAP + slot] = enc;
    }
}

// ---------------------------------------------------------------------------
__device__ __forceinline__ uint32_t smem_u32(const void* p) {
    uint32_t a;
    asm("{ .reg .u64 tmp; cvta.to.shared.u64 tmp, %1; cvt.u32.u64 %0, tmp; }"
        : "=r"(a) : "l"(p));
    return a;
}
__device__ __forceinline__ void cp16(uint32_t dst, const void* src) {
    asm volatile("cp.async.cg.shared.global [%0], [%1], 16;"
                 :: "r"(dst), "l"(src));
}
__device__ __forceinline__ void issue_row(uint32_t sdst_base, const float* grow,
                                          int lane) {
    const char* src = reinterpret_cast<const char*>(grow) + lane * 16;
    uint32_t    dst = sdst_base + lane * 16;
#pragma unroll
    for (int j = 0; j < 6; j++)
        cp16(dst + j * 512, src + j * 512);
}

// ---------------------------------------------------------------------------
// Block per tag, 8 warps, private 2-stage cp.async ring per warp (3KB/stage).
// Each lane copies exactly the bytes it later reads -> per-thread wait_group,
// no warp barriers in the hot loop. 52224B dyn smem -> 4 blocks/SM.
// Cursor: tid0 reads + resets (sole reset point), broadcast via shared.
// ---------------------------------------------------------------------------
__global__ __launch_bounds__(256) void edge_kernel(
    const float* __restrict__ h_tag,
    const float* __restrict__ h_video,
    float*       __restrict__ cls,
    float*       __restrict__ labels)
{
    extern __shared__ float4 smem[];
    float4* stag = smem;                 // [0, 192)
    float4* ring = smem + ROW_F4;        // 16 stages of 192
    __shared__ int s_n;

    const int t    = blockIdx.x;
    const int tid  = threadIdx.x;
    const int lane = tid & 31;
    const int warp = tid >> 5;

    if (tid == 0) {
        int c = g_cursor[t];
        s_n = (c > BIN_CAP) ? BIN_CAP : c;
        g_cursor[t] = 0;                 // reset for next replay's scatter
    }
    if (tid < ROW_F4)
        stag[tid] = reinterpret_cast<const float4*>(h_tag + (size_t)t * D_DIM)[tid];
    __syncthreads();

    // tag row -> registers
    float4 ta0 = stag[lane +   0];
    float4 ta1 = stag[lane +  32];
    float4 ta2 = stag[lane +  64];
    float4 ta3 = stag[lane +  96];
    float4 ta4 = stag[lane + 128];
    float4 ta5 = stag[lane + 160];

    const int n = s_n;
    const unsigned* elist = g_edges + (size_t)t * BIN_CAP;

    float4*  st0 = ring + (size_t)(warp * STAGES + 0) * ROW_F4;
    float4*  st1 = ring + (size_t)(warp * STAGES + 1) * ROW_F4;
    uint32_t sb0 = smem_u32(st0);
    uint32_t sb1 = smem_u32(st1);

    // prologue: fill both stages
    int nextE = warp;
#pragma unroll
    for (int s = 0; s < STAGES; s++) {
        if (nextE < n) {
            unsigned enc = elist[nextE];
            issue_row(s ? sb1 : sb0,
                      h_video + (size_t)(enc & 0x7fffffffu) * D_DIM, lane);
        }
        asm volatile("cp.async.commit_group;");
        nextE += 8;
    }

    int s = 0;
    for (int cur = warp; cur < n; cur += 8) {
        asm volatile("cp.async.wait_group 1;");   // oldest stage ready

        unsigned enc = elist[cur];
        const float4* B = s ? st1 : st0;
        float4 v0 = B[lane +   0];
        float4 v1 = B[lane +  32];
        float4 v2 = B[lane +  64];
        float4 v3 = B[lane +  96];
        float4 v4 = B[lane + 128];
        float4 v5 = B[lane + 160];

        float acc;
        acc  = ta0.x * v0.x + ta0.y * v0.y + ta0.z * v0.z + ta0.w * v0.w;
        acc += ta1.x * v1.x + ta1.y * v1.y + ta1.z * v1.z + ta1.w * v1.w;
        acc += ta2.x * v2.x + ta2.y * v2.y + ta2.z * v2.z + ta2.w * v2.w;
        acc += ta3.x * v3.x + ta3.y * v3.y + ta3.z * v3.z + ta3.w * v3.w;
        acc += ta4.x * v4.x + ta4.y * v4.y + ta4.z * v4.z + ta4.w * v4.w;
        acc += ta5.x * v5.x + ta5.y * v5.y + ta5.z * v5.z + ta5.w * v5.w;

#pragma unroll
        for (int o = 16; o > 0; o >>= 1)
            acc += __shfl_xor_sync(0xffffffffu, acc, o);

        if (lane == 0) {
            int d = (int)(enc & 0x7fffffffu);
            size_t cell = (size_t)d * T_DIM + (size_t)t;
            atomicAdd(&cls[cell], acc);
            if (enc & 0x80000000u) atomicAdd(&labels[cell], 1.0f);
        }

        // refill the stage we just consumed
        if (nextE < n) {
            unsigned enc_n = elist[nextE];
            issue_row(s ? sb1 : sb0,
                      h_video + (size_t)(enc_n & 0x7fffffffu) * D_DIM, lane);
        }
        asm volatile("cp.async.commit_group;");
        nextE += 8;
        s ^= 1;
    }

    asm volatile("cp.async.wait_all;");
}

// ---------------------------------------------------------------------------
extern "C" void kernel_launch(void* const* d_in, const int* in_sizes, int n_in,
                              void* d_out, int out_size)
{
    const float* h_tag   = (const float*)d_in[0];
    const float* h_video = (const float*)d_in[1];
    const int*   pos_src = (const int*)d_in[2];
    const int*   pos_dst = (const int*)d_in[3];
    const int*   neg_src = (const int*)d_in[4];
    const int*   neg_dst = (const int*)d_in[5];

    const int nPos = in_sizes[2];
    const int nNeg = in_sizes[4];
    const int nTot = nPos + nNeg;

    float* cls    = (float*)d_out;
    long long vt  = (long long)out_size / 2;
    float* labels = cls + vt;

    const int smem_bytes = (ROW_F4 + 8 * STAGES * ROW_F4) * sizeof(float4); // 52224

    // One-time host-side setup (first call is the uncaptured correctness run,
    // so no resource creation happens during graph capture).
    static cudaStream_t s2  = nullptr;
    static cudaEvent_t  evA = nullptr, evB = nullptr;
    if (s2 == nullptr) {
        cudaStreamCreate(&s2);
        cudaEventCreateWithFlags(&evA, cudaEventDisableTiming);
        cudaEventCreateWithFlags(&evB, cudaEventDisableTiming);
        cudaFuncSetAttribute(edge_kernel,
                             cudaFuncAttributeMaxDynamicSharedMemorySize, smem_bytes);
    }

    // Fork: scatter runs on s2 concurrently with zero on the main stream.
    cudaEventRecord(evA, 0);
    cudaStreamWaitEvent(s2, evA, 0);

    scatter_kernel<<<(nTot + 255) / 256, 256, 0, s2>>>(
        pos_src, pos_dst, neg_src, neg_dst, nPos, nTot);
    cudaEventRecord(evB, s2);

    {
        long long nvec = (long long)out_size / 4;
        long long blocks = (nvec + 255) / 256;
        zero_kernel<<<(unsigned)blocks, 256>>>((float4*)d_out, nvec);
    }

    // Join: edge needs both the zeroed output and the filled bins.
    cudaStreamWaitEvent(0, evB, 0);
    edge_kernel<<<T_DIM, 256, smem_bytes>>>(h_tag, h_video, cls, labels);
}

// round 16
// speedup vs baseline: 1.0089x; 1.0089x over previous
#include <cuda_runtime.h>
#include <cstdint>

// T = 2000 tags, V = 20000 videos, D = 768, E_POS = E_NEG = 100000
// Output layout: [cls_score (V*T f32), labels (V*T f32)]
//
// R16 = R14 (zero 43us DRAM floor + cp.async edge ~52us LTS floor) with the
// scatter rebuilt: 8 sub-bins per tag (16000 counters spread across L2
// slices -> kills the per-address atomic-ALU serialization that pinned
// scatter at 13.5us). The edge kernel consumes the 8 sub-bins as ONE
// virtual list via a shared prefix table, preserving per-warp balance.
// Cursor lifecycle: zero resets all cursors -> scatter fills -> edge READS.

#define D_DIM    768
#define T_DIM    2000
#define BIN_SUB  8
#define SUB_CAP  48      // Poisson(12.5)/sub-bin; P(>48) ~ 1e-11
#define NCUR     (T_DIM * BIN_SUB)
#define STAGES   2
#define ROW_F4   (D_DIM / 4)     // 192 float4 per row (3072 B)

__device__ int      g_cursor[NCUR];              // zero at module load
__device__ unsigned g_edges [NCUR * SUB_CAP];    // bit31 = isPos, low = dst

// ---------------------------------------------------------------------------
__global__ void zero_kernel(float4* __restrict__ out, long long nvec) {
    long long i = (long long)blockIdx.x * blockDim.x + threadIdx.x;
    if (i < nvec)
        __stcs(&out[i], make_float4(0.f, 0.f, 0.f, 0.f));
    if (i < NCUR) g_cursor[(int)i] = 0;     // reset cursors for this replay
}

// ---------------------------------------------------------------------------
__global__ void scatter_kernel(const int* __restrict__ pos_src,
                               const int* __restrict__ pos_dst,
                               const int* __restrict__ neg_src,
                               const int* __restrict__ neg_dst,
                               int nPos, int nTot) {
    int i = blockIdx.x * blockDim.x + threadIdx.x;
    if (i < nTot) {
        int t; unsigned enc;
        if (i < nPos) { t = pos_src[i];        enc = (unsigned)pos_dst[i] | 0x80000000u; }
        else          { t = neg_src[i - nPos]; enc = (unsigned)neg_dst[i - nPos]; }
        int cidx = t * BIN_SUB + (i & (BIN_SUB - 1));
        int slot = atomicAdd(&g_cursor[cidx], 1);
        if (slot < SUB_CAP)
            g_edges[cidx * SUB_CAP + slot] = enc;
    }
}

// ---------------------------------------------------------------------------
__device__ __forceinline__ uint32_t smem_u32(const void* p) {
    uint32_t a;
    asm("{ .reg .u64 tmp; cvta.to.shared.u64 tmp, %1; cvt.u32.u64 %0, tmp; }"
        : "=r"(a) : "l"(p));
    return a;
}
__device__ __forceinline__ void cp16(uint32_t dst, const void* src) {
    asm volatile("cp.async.cg.shared.global [%0], [%1], 16;"
                 :: "r"(dst), "l"(src));
}
__device__ __forceinline__ void issue_row(uint32_t sdst_base, const float* grow,
                                          int lane) {
    const char* src = reinterpret_cast<const char*>(grow) + lane * 16;
    uint32_t    dst = sdst_base + lane * 16;
#pragma unroll
    for (int j = 0; j < 6; j++)
        cp16(dst + j * 512, src + j * 512);
}

// ---------------------------------------------------------------------------
// Block per tag, 8 warps, private 2-stage cp.async ring per warp.
// The 8 sub-bins are exposed as one virtual list [0, n) via s_off[]:
// virtual index i lives in bin b where s_off[b] <= i < s_off[b+1], at slot
// i - s_off[b]. Warps stride the virtual list (w, w+8, ...) -> balanced.
// ---------------------------------------------------------------------------
__global__ __launch_bounds__(256) void edge_kernel(
    const float* __restrict__ h_tag,
    const float* __restrict__ h_video,
    float*       __restrict__ cls,
    float*       __restrict__ labels)
{
    extern __shared__ float4 smem[];
    float4* stag = smem;                 // [0, 192)
    float4* ring = smem + ROW_F4;        // 16 stages of 192
    __shared__ int s_off[BIN_SUB + 1];

    const int t    = blockIdx.x;
    const int tid  = threadIdx.x;
    const int lane = tid & 31;
    const int warp = tid >> 5;

    if (tid == 0) {
        int acc = 0;
        s_off[0] = 0;
#pragma unroll
        for (int b = 0; b < BIN_SUB; b++) {
            int c = g_cursor[t * BIN_SUB + b];      // READ ONLY (zero resets)
            if (c > SUB_CAP) c = SUB_CAP;
            acc += c;
            s_off[b + 1] = acc;
        }
    }
    if (tid < ROW_F4)
        stag[tid] = reinterpret_cast<const float4*>(h_tag + (size_t)t * D_DIM)[tid];
    __syncthreads();

    // tag row -> registers
    float4 ta0 = stag[lane +   0];
    float4 ta1 = stag[lane +  32];
    float4 ta2 = stag[lane +  64];
    float4 ta3 = stag[lane +  96];
    float4 ta4 = stag[lane + 128];
    float4 ta5 = stag[lane + 160];

    const int n = s_off[BIN_SUB];
    const unsigned* base = g_edges + (size_t)t * BIN_SUB * SUB_CAP;

    // virtual-index -> encoded edge (all lanes compute identically; s_off in smem)
    auto fetch = [&](int i) -> unsigned {
        int b = 0;
#pragma unroll
        for (int k = 0; k < BIN_SUB - 1; k++)
            if (i >= s_off[b + 1]) b++;
        return base[b * SUB_CAP + (i - s_off[b])];
    };

    float4*  st0 = ring + (size_t)(warp * STAGES + 0) * ROW_F4;
    float4*  st1 = ring + (size_t)(warp * STAGES + 1) * ROW_F4;
    uint32_t sb0 = smem_u32(st0);
    uint32_t sb1 = smem_u32(st1);

    // prologue: fill both stages
    unsigned encQ[STAGES] = {0, 0};
    int nextE = warp;
#pragma unroll
    for (int s = 0; s < STAGES; s++) {
        if (nextE < n) {
            unsigned enc = fetch(nextE);
            encQ[s] = enc;
            issue_row(s ? sb1 : sb0,
                      h_video + (size_t)(enc & 0x7fffffffu) * D_DIM, lane);
        }
        asm volatile("cp.async.commit_group;");
        nextE += 8;
    }

    int s = 0;
    for (int cur = warp; cur < n; cur += 8) {
        asm volatile("cp.async.wait_group 1;");   // oldest stage ready

        unsigned enc = encQ[s];
        const float4* B = s ? st1 : st0;
        float4 v0 = B[lane +   0];
        float4 v1 = B[lane +  32];
        float4 v2 = B[lane +  64];
        float4 v3 = B[lane +  96];
        float4 v4 = B[lane + 128];
        float4 v5 = B[lane + 160];

        float acc;
        acc  = ta0.x * v0.x + ta0.y * v0.y + ta0.z * v0.z + ta0.w * v0.w;
        acc += ta1.x * v1.x + ta1.y * v1.y + ta1.z * v1.z + ta1.w * v1.w;
        acc += ta2.x * v2.x + ta2.y * v2.y + ta2.z * v2.z + ta2.w * v2.w;
        acc += ta3.x * v3.x + ta3.y * v3.y + ta3.z * v3.z + ta3.w * v3.w;
        acc += ta4.x * v4.x + ta4.y * v4.y + ta4.z * v4.z + ta4.w * v4.w;
        acc += ta5.x * v5.x + ta5.y * v5.y + ta5.z * v5.z + ta5.w * v5.w;

#pragma unroll
        for (int o = 16; o > 0; o >>= 1)
            acc += __shfl_xor_sync(0xffffffffu, acc, o);

        if (lane == 0) {
            int d = (int)(enc & 0x7fffffffu);
            size_t cell = (size_t)d * T_DIM + (size_t)t;
            atomicAdd(&cls[cell], acc);
            if (enc & 0x80000000u) atomicAdd(&labels[cell], 1.0f);
        }

        // refill the stage we just consumed
        if (nextE < n) {
            unsigned enc_n = fetch(nextE);
            encQ[s] = enc_n;
            issue_row(s ? sb1 : sb0,
                      h_video + (size_t)(enc_n & 0x7fffffffu) * D_DIM, lane);
        }
        asm volatile("cp.async.commit_group;");
        nextE += 8;
        s ^= 1;
    }

    asm volatile("cp.async.wait_all;");
}

// ---------------------------------------------------------------------------
extern "C" void kernel_launch(void* const* d_in, const int* in_sizes, int n_in,
                              void* d_out, int out_size)
{
    const float* h_tag   = (const float*)d_in[0];
    const float* h_video = (const float*)d_in[1];
    const int*   pos_src = (const int*)d_in[2];
    const int*   pos_dst = (const int*)d_in[3];
    const int*   neg_src = (const int*)d_in[4];
    const int*   neg_dst = (const int*)d_in[5];

    const int nPos = in_sizes[2];
    const int nNeg = in_sizes[4];
    const int nTot = nPos + nNeg;

    float* cls    = (float*)d_out;
    long long vt  = (long long)out_size / 2;
    float* labels = cls + vt;

    const int smem_bytes = (ROW_F4 + 8 * STAGES * ROW_F4) * sizeof(float4); // 52224

    static bool init = false;
    if (!init) {
        init = true;
        cudaFuncSetAttribute(edge_kernel,
                             cudaFuncAttributeMaxDynamicSharedMemorySize, smem_bytes);
    }

    // 1) zero output + reset cursors (DRAM-write-bound, ~43us)
    {
        long long nvec = (long long)out_size / 4;
        long long blocks = (nvec + 255) / 256;
        zero_kernel<<<(unsigned)blocks, 256>>>((float4*)d_out, nvec);
    }

    // 2) sub-binned scatter (16000 counters -> no atomic-slice serialization)
    scatter_kernel<<<(nTot + 255) / 256, 256>>>(pos_src, pos_dst, neg_src, neg_dst,
                                                nPos, nTot);

    // 3) edge gather with cp.async pipeline over the virtual list
    edge_kernel<<<T_DIM, 256, smem_bytes>>>(h_tag, h_video, cls, labels);
}

// round 17
// speedup vs baseline: 1.1422x; 1.1321x over previous
#include <cuda_runtime.h>
#include <cstdint>

// T = 2000 tags, V = 20000 videos, D = 768, E_POS = E_NEG = 100000
// Output layout: [cls_score (V*T f32), labels (V*T f32)]
//
// R17 = R14's proven pipeline + R16's sub-binned scatter, joined by a
// one-shot shared-memory COMPACTION instead of R16's per-fetch virtual-list
// translation (which spilled encQ to local memory and added a branchy smem
// search to every issue -> +45us).
//   K1 zero_kernel   : 320MB evict-first stream + reset 16000 cursors (~43us)
//   K2 scatter_kernel: bin by (tag, i&7) -> 16000 counters, ~25 atomics each
//                      (~4-5us; single-counter-per-tag was 13.5us of L2
//                      atomic-ALU serialization)
//   K3 edge_kernel   : block per tag. Startup: warp w copies sub-bin w into
//                      a contiguous shared list (one pass). Hot loop: R14's
//                      per-warp 2-stage cp.async ring, elist now in smem.
// Cursor lifecycle: zero resets -> scatter fills -> edge READS ONLY.

#define D_DIM    768
#define T_DIM    2000
#define BIN_SUB  8
#define SUB_CAP  48      // Poisson(12.5)/sub-bin; P(>48) ~ 1e-11
#define NCUR     (T_DIM * BIN_SUB)
#define STAGES   2
#define ROW_F4   (D_DIM / 4)     // 192 float4 per row (3072 B)

__device__ int      g_cursor[NCUR];              // zero at module load
__device__ unsigned g_edges [NCUR * SUB_CAP];    // bit31 = isPos, low = dst

// ---------------------------------------------------------------------------
__global__ void zero_kernel(float4* __restrict__ out, long long nvec) {
    long long i = (long long)blockIdx.x * blockDim.x + threadIdx.x;
    if (i < nvec)
        __stcs(&out[i], make_float4(0.f, 0.f, 0.f, 0.f));
    if (i < NCUR) g_cursor[(int)i] = 0;     // reset cursors for this replay
}

// ---------------------------------------------------------------------------
__global__ void scatter_kernel(const int* __restrict__ pos_src,
                               const int* __restrict__ pos_dst,
                               const int* __restrict__ neg_src,
                               const int* __restrict__ neg_dst,
                               int nPos, int nTot) {
    int i = blockIdx.x * blockDim.x + threadIdx.x;
    if (i < nTot) {
        int t; unsigned enc;
        if (i < nPos) { t = pos_src[i];        enc = (unsigned)pos_dst[i] | 0x80000000u; }
        else          { t = neg_src[i - nPos]; enc = (unsigned)neg_dst[i - nPos]; }
        int cidx = t * BIN_SUB + (i & (BIN_SUB - 1));
        int slot = atomicAdd(&g_cursor[cidx], 1);
        if (slot < SUB_CAP)
            g_edges[cidx * SUB_CAP + slot] = enc;
    }
}

// ---------------------------------------------------------------------------
__device__ __forceinline__ uint32_t smem_u32(const void* p) {
    uint32_t a;
    asm("{ .reg .u64 tmp; cvta.to.shared.u64 tmp, %1; cvt.u32.u64 %0, tmp; }"
        : "=r"(a) : "l"(p));
    return a;
}
__device__ __forceinline__ void cp16(uint32_t dst, const void* src) {
    asm volatile("cp.async.cg.shared.global [%0], [%1], 16;"
                 :: "r"(dst), "l"(src));
}
__device__ __forceinline__ void issue_row(uint32_t sdst_base, const float* grow,
                                          int lane) {
    const char* src = reinterpret_cast<const char*>(grow) + lane * 16;
    uint32_t    dst = sdst_base + lane * 16;
#pragma unroll
    for (int j = 0; j < 6; j++)
        cp16(dst + j * 512, src + j * 512);
}

// ---------------------------------------------------------------------------
// Block per tag, 8 warps, private 2-stage cp.async ring per warp (3KB/stage).
// Startup: compact the 8 sub-bins into contiguous s_list (warp w copies bin w).
// Hot loop = R14 verbatim, with the edge list in shared memory.
// Dyn smem 52224B + ~1.6KB static -> 4 blocks/SM.
// ---------------------------------------------------------------------------
__global__ __launch_bounds__(256) void edge_kernel(
    const float* __restrict__ h_tag,
    const float* __restrict__ h_video,
    float*       __restrict__ cls,
    float*       __restrict__ labels)
{
    extern __shared__ float4 smem[];
    float4* stag = smem;                 // [0, 192)
    float4* ring = smem + ROW_F4;        // 16 stages of 192

    __shared__ int      s_off [BIN_SUB + 1];
    __shared__ unsigned s_list[BIN_SUB * SUB_CAP];   // compacted edge list

    const int t    = blockIdx.x;
    const int tid  = threadIdx.x;
    const int lane = tid & 31;
    const int warp = tid >> 5;

    if (tid == 0) {
        int acc = 0;
        s_off[0] = 0;
#pragma unroll
        for (int b = 0; b < BIN_SUB; b++) {
            int c = g_cursor[t * BIN_SUB + b];      // READ ONLY (zero resets)
            if (c > SUB_CAP) c = SUB_CAP;
            acc += c;
            s_off[b + 1] = acc;
        }
    }
    if (tid < ROW_F4)
        stag[tid] = reinterpret_cast<const float4*>(h_tag + (size_t)t * D_DIM)[tid];
    __syncthreads();

    // compaction: warp w copies sub-bin w into s_list[s_off[w] ..)
    {
        const unsigned* src = g_edges + (size_t)(t * BIN_SUB + warp) * SUB_CAP;
        int beg = s_off[warp];
        int cnt = s_off[warp + 1] - beg;
        for (int s = lane; s < cnt; s += 32)
            s_list[beg + s] = src[s];
    }
    __syncthreads();

    // tag row -> registers
    float4 ta0 = stag[lane +   0];
    float4 ta1 = stag[lane +  32];
    float4 ta2 = stag[lane +  64];
    float4 ta3 = stag[lane +  96];
    float4 ta4 = stag[lane + 128];
    float4 ta5 = stag[lane + 160];

    const int n = s_off[BIN_SUB];

    float4*  st0 = ring + (size_t)(warp * STAGES + 0) * ROW_F4;
    float4*  st1 = ring + (size_t)(warp * STAGES + 1) * ROW_F4;
    uint32_t sb0 = smem_u32(st0);
    uint32_t sb1 = smem_u32(st1);

    // prologue: fill both stages
    int nextE = warp;
#pragma unroll
    for (int s = 0; s < STAGES; s++) {
        if (nextE < n) {
            unsigned enc = s_list[nextE];
            issue_row(s ? sb1 : sb0,
                      h_video + (size_t)(enc & 0x7fffffffu) * D_DIM, lane);
        }
        asm volatile("cp.async.commit_group;");
        nextE += 8;
    }

    int s = 0;
    for (int cur = warp; cur < n; cur += 8) {
        asm volatile("cp.async.wait_group 1;");   // oldest stage ready

        unsigned enc = s_list[cur];
        const float4* B = s ? st1 : st0;
        float4 v0 = B[lane +   0];
        float4 v1 = B[lane +  32];
        float4 v2 = B[lane +  64];
        float4 v3 = B[lane +  96];
        float4 v4 = B[lane + 128];
        float4 v5 = B[lane + 160];

        float acc;
        acc  = ta0.x * v0.x + ta0.y * v0.y + ta0.z * v0.z + ta0.w * v0.w;
        acc += ta1.x * v1.x + ta1.y * v1.y + ta1.z * v1.z + ta1.w * v1.w;
        acc += ta2.x * v2.x + ta2.y * v2.y + ta2.z * v2.z + ta2.w * v2.w;
        acc += ta3.x * v3.x + ta3.y * v3.y + ta3.z * v3.z + ta3.w * v3.w;
        acc += ta4.x * v4.x + ta4.y * v4.y + ta4.z * v4.z + ta4.w * v4.w;
        acc += ta5.x * v5.x + ta5.y * v5.y + ta5.z * v5.z + ta5.w * v5.w;

#pragma unroll
        for (int o = 16; o > 0; o >>= 1)
            acc += __shfl_xor_sync(0xffffffffu, acc, o);

        if (lane == 0) {
            int d = (int)(enc & 0x7fffffffu);
            size_t cell = (size_t)d * T_DIM + (size_t)t;
            atomicAdd(&cls[cell], acc);
            if (enc & 0x80000000u) atomicAdd(&labels[cell], 1.0f);
        }

        // refill the stage we just consumed
        if (nextE < n) {
            unsigned enc_n = s_list[nextE];
            issue_row(s ? sb1 : sb0,
                      h_video + (size_t)(enc_n & 0x7fffffffu) * D_DIM, lane);
        }
        asm volatile("cp.async.commit_group;");
        nextE += 8;
        s ^= 1;
    }

    asm volatile("cp.async.wait_all;");
}

// ---------------------------------------------------------------------------
extern "C" void kernel_launch(void* const* d_in, const int* in_sizes, int n_in,
                              void* d_out, int out_size)
{
    const float* h_tag   = (const float*)d_in[0];
    const float* h_video = (const float*)d_in[1];
    const int*   pos_src = (const int*)d_in[2];
    const int*   pos_dst = (const int*)d_in[3];
    const int*   neg_src = (const int*)d_in[4];
    const int*   neg_dst = (const int*)d_in[5];

    const int nPos = in_sizes[2];
    const int nNeg = in_sizes[4];
    const int nTot = nPos + nNeg;

    float* cls    = (float*)d_out;
    long long vt  = (long long)out_size / 2;
    float* labels = cls + vt;

    const int smem_bytes = (ROW_F4 + 8 * STAGES * ROW_F4) * sizeof(float4); // 52224

    static bool init = false;
    if (!init) {
        init = true;
        cudaFuncSetAttribute(edge_kernel,
                             cudaFuncAttributeMaxDynamicSharedMemorySize, smem_bytes);
    }

    // 1) zero output + reset cursors (DRAM-write-bound, ~43us)
    {
        long long nvec = (long long)out_size / 4;
        long long blocks = (nvec + 255) / 256;
        zero_kernel<<<(unsigned)blocks, 256>>>((float4*)d_out, nvec);
    }

    // 2) sub-binned scatter (~4-5us)
    scatter_kernel<<<(nTot + 255) / 256, 256>>>(pos_src, pos_dst, neg_src, neg_dst,
                                                nPos, nTot);

    // 3) edge gather: compact sub-bins to smem, then R14's cp.async pipeline
    edge_kernel<<<T_DIM, 256, smem_bytes>>>(h_tag, h_video, cls, labels);
}